// round 15
// baseline (speedup 1.0000x reference)
#include <cuda_runtime.h>
#include <cuda_bf16.h>
#include <cuda_fp16.h>
#include <cstdint>
#include <math.h>

#define Bv 64
#define Tv 512
#define Iv 1024
#define Hv 1024
#define Gv 4096   // 4*H

// ---------------------------------------------------------------------------
// Static device scratch (all fp16)
// ---------------------------------------------------------------------------
__device__ __half g_Gx[(size_t)Tv * Bv * Gv];             // 256MB [T][B][4H]
__device__ __half g_x_f16[(size_t)Bv * Tv * Iv];          // 64MB
__device__ __half g_Wih_f16[(size_t)Gv * Iv];             // 8MB
__device__ __half g_Whh_f16[(size_t)Gv * Hv];             // 8MB
__device__ __half g_h[2][Bv * Hv];                        // fp16 h
__device__ unsigned int g_bar4[4];                        // [batch-group][row-half]

// ---------------------------------------------------------------------------
// Helpers
// ---------------------------------------------------------------------------
__device__ __forceinline__ uint32_t smem_u32(const void* p) {
    uint32_t a;
    asm("{ .reg .u64 t; cvta.to.shared.u64 t, %1; cvt.u32.u64 %0, t; }"
        : "=r"(a) : "l"(p));
    return a;
}

#define SWZ128(o) ((o) ^ (((o) >> 3) & 0x70))

__device__ __forceinline__ void cp16(uint32_t dst, const void* src) {
    asm volatile("cp.async.cg.shared.global [%0], [%1], 16;" :: "r"(dst), "l"(src));
}
#define CP_COMMIT() asm volatile("cp.async.commit_group;" ::: "memory")
#define CP_WAIT(n)  asm volatile("cp.async.wait_group %0;" :: "n"(n) : "memory")

__device__ __forceinline__ void ldsm4(uint32_t* r, uint32_t addr) {
    asm volatile("ldmatrix.sync.aligned.m8n8.x4.shared.b16 {%0,%1,%2,%3}, [%4];"
        : "=r"(r[0]), "=r"(r[1]), "=r"(r[2]), "=r"(r[3]) : "r"(addr));
}

__device__ __forceinline__ void mma16816h(float* d, const uint32_t* a,
                                          uint32_t b0, uint32_t b1) {
    asm volatile(
        "mma.sync.aligned.m16n8k16.row.col.f32.f16.f16.f32 "
        "{%0,%1,%2,%3}, {%4,%5,%6,%7}, {%8,%9}, {%0,%1,%2,%3};"
        : "+f"(d[0]), "+f"(d[1]), "+f"(d[2]), "+f"(d[3])
        : "r"(a[0]), "r"(a[1]), "r"(a[2]), "r"(a[3]), "r"(b0), "r"(b1));
}

__device__ __forceinline__ float sigm(float x) {
    return 1.0f / (1.0f + __expf(-x));
}
__device__ __forceinline__ float tanh_fast(float x) {
    float cx = fminf(fmaxf(x, -10.0f), 10.0f);
    float e = __expf(2.0f * cx);
    return (e - 1.0f) / (e + 1.0f);
}

// ---------------------------------------------------------------------------
// fp16 single-pass warp MMA over one 64-wide K sub-tile.
// MT m-tiles of 16 rows, NT n-tiles of 16 cols.
// ---------------------------------------------------------------------------
template <int MT, int NT>
__device__ __forceinline__ void warp_mma_f16(
    uint32_t aT, uint32_t bT, int mrow, int nbase, int lane, float acc[][4])
{
    const int arowoff = (lane & 7) + ((lane >> 3) & 1) * 8;
    const int nrowoff = (lane & 7) + ((lane >> 4) & 1) * 8;
    #pragma unroll
    for (int kk = 0; kk < 4; kk++) {
        uint32_t ah[MT][4], bw[NT][4];
        const int akoff = kk * 32 + (lane >> 4) * 16;
        const int bkoff = kk * 32 + ((lane >> 3) & 1) * 16;
        #pragma unroll
        for (int m = 0; m < MT; m++) {
            uint32_t off = SWZ128((uint32_t)((mrow + m * 16 + arowoff) * 128 + akoff));
            ldsm4(ah[m], aT + off);
        }
        #pragma unroll
        for (int jb = 0; jb < NT; jb++) {
            uint32_t off = SWZ128((uint32_t)((nbase + jb * 16 + nrowoff) * 128 + bkoff));
            ldsm4(bw[jb], bT + off);
        }
        #pragma unroll
        for (int jb = 0; jb < NT; jb++)
            #pragma unroll
            for (int m = 0; m < MT; m++) {
                mma16816h(acc[m * 2 * NT + jb * 2],     ah[m], bw[jb][0], bw[jb][1]);
                mma16816h(acc[m * 2 * NT + jb * 2 + 1], ah[m], bw[jb][2], bw[jb][3]);
            }
    }
}

// ---------------------------------------------------------------------------
// Fused prep (device symbols bound in device code — R3 lesson).
// ---------------------------------------------------------------------------
__global__ void prep_all(const float* __restrict__ x,
                         const float* __restrict__ Wih,
                         const float* __restrict__ Whh) {
    const size_t NX = (size_t)Bv * Tv * Iv;
    const size_t NW = (size_t)Gv * Iv;
    size_t gid = (size_t)blockIdx.x * blockDim.x + threadIdx.x;
    size_t stride = (size_t)gridDim.x * blockDim.x;
    for (size_t i = gid; i < NX; i += stride) g_x_f16[i]   = __float2half(x[i]);
    for (size_t i = gid; i < NW; i += stride) g_Wih_f16[i] = __float2half(Wih[i]);
    for (size_t i = gid; i < NW; i += stride) g_Whh_f16[i] = __float2half(Whh[i]);
    for (size_t i = gid; i < (size_t)Bv * Hv; i += stride) g_h[0][i] = __float2half(0.0f);
    if (gid < 4) g_bar4[gid] = 0u;
}

__global__ void dummy_kernel() {}

// ---------------------------------------------------------------------------
// Input GEMM (fp16 single-pass HMMA, proven R12-R14)
// ---------------------------------------------------------------------------
#define G_STAGE 32768
#define G_SMEM  (2 * G_STAGE)

__device__ __forceinline__ void gemm_load(uint32_t sb, int s, int k0,
                                          int m0, int n0, int tid) {
    uint32_t base = sb + (uint32_t)s * G_STAGE;
    #pragma unroll
    for (int r = 0; r < 4; r++) {
        int idx = tid + r * 256;
        int row = idx >> 3, c = idx & 7;
        cp16(base + SWZ128((uint32_t)(row * 128 + c * 16)),
             g_x_f16 + (size_t)(m0 + row) * Iv + k0 + c * 8);
    }
    #pragma unroll
    for (int r = 0; r < 4; r++) {
        int idx = tid + r * 256;
        int row = idx >> 3, c = idx & 7;
        cp16(base + 16384 + SWZ128((uint32_t)(row * 128 + c * 16)),
             g_Wih_f16 + (size_t)(n0 + row) * Iv + k0 + c * 8);
    }
}

__global__ void __launch_bounds__(256, 1) gemm_in_mma(const float* __restrict__ bias)
{
    extern __shared__ char smem[];
    uint32_t sb = smem_u32(smem);
    const int tid = threadIdx.x, lane = tid & 31, wid = tid >> 5;
    const int m0 = blockIdx.y * 128, n0 = blockIdx.x * 128;

    float acc[16][4];
    #pragma unroll
    for (int i = 0; i < 16; i++)
        #pragma unroll
        for (int j = 0; j < 4; j++) acc[i][j] = 0.0f;

    gemm_load(sb, 0, 0, m0, n0, tid);
    CP_COMMIT();

    const int mrow = (wid & 3) * 32, nbase = (wid >> 2) * 64;
    for (int it = 0; it < 16; it++) {
        const int s = it & 1;
        if (it + 1 < 16) {
            gemm_load(sb, (it + 1) & 1, (it + 1) * 64, m0, n0, tid);
            CP_COMMIT();
            CP_WAIT(1);
        } else {
            CP_WAIT(0);
        }
        __syncthreads();
        uint32_t base = sb + (uint32_t)s * G_STAGE;
        warp_mma_f16<2, 4>(base, base + 16384, mrow, nbase, lane, acc);
        __syncthreads();
    }

    #pragma unroll
    for (int m = 0; m < 2; m++)
        #pragma unroll
        for (int j = 0; j < 8; j++) {
            float* a = acc[m * 8 + j];
            int gr = m0 + (wid & 3) * 32 + m * 16 + (lane >> 2);
            int n  = n0 + (wid >> 2) * 64 + j * 8 + 2 * (lane & 3);
            float b0 = bias[n], b1 = bias[n + 1];
            int bi0 = gr >> 9, tt0 = gr & 511;
            __half2* o0 = (__half2*)(g_Gx + ((size_t)tt0 * Bv + bi0) * Gv + n);
            *o0 = __floats2half2_rn(a[0] + b0, a[1] + b1);
            int gr2 = gr + 8, bi2 = gr2 >> 9, tt2 = gr2 & 511;
            __half2* o2 = (__half2*)(g_Gx + ((size_t)tt2 * Bv + bi2) * Gv + n);
            *o2 = __floats2half2_rn(a[2] + b0, a[3] + b1);
        }
}

// ---------------------------------------------------------------------------
// Persistent LSTM recurrence, R15 batch-split INSIDE the CTA:
// 128 CTAs = 2 batch-groups x 64. CTA = 32 batch rows x 16 hidden cols.
// Group g (128 thr) owns rows g*16..g*16+15 over FULL K — no cross-group
// reduction, no CTA-wide sync in the step loop. Warp = m16 x n16 (one gate).
// 4 chunks of K=256 (8KB), 3 bufs, lookahead-2. Per-(bg,g) global counters.
// ---------------------------------------------------------------------------
#define WS     0                           /* 16 sub-chunks x 8KB = 128KB */
#define AB     131072                      /* 2 grp x 3 bufs x 8KB = 48KB */
#define GXS    (AB + 6 * 8192)             /* 180224: 2 grp x 2 buf x 2304 */
#define CS     (GXS + 4 * 2304)            /* 189440: 512 fp32 = 2KB */
#define GS     (CS + 2048)                 /* 191488: 2 grp x 16x66 fp32 */
#define P_SMEM (GS + 2 * 4224)             /* 199936 (~195.3KB) */

// Group loads one K-chunk of 256 for its 16 rows (4 sub-chunks x 2KB = 8KB).
__device__ __forceinline__ void group_loadA(uint32_t sb, int gbuf, int k0,
                                            const __half* __restrict__ hIn,
                                            int rowbase, int gtid) {
    uint32_t base = sb + AB + (uint32_t)gbuf * 8192;
    #pragma unroll
    for (int r = 0; r < 4; r++) {          // 512 cp16 = 8KB
        int idx = gtid + r * 128;
        int sub = idx >> 7, rem = idx & 127;
        int row = rem >> 3, c = rem & 7;   // row 0..15
        const __half* src = hIn + (size_t)(rowbase + row) * Hv + k0 + sub * 64 + c * 8;
        cp16(base + sub * 2048 + SWZ128((uint32_t)(row * 128 + c * 16)), src);
    }
}

// Group-private Gx prefetch: 16 rows x 64 gate cols fp16 (2KB, stride 144B).
__device__ __forceinline__ void load_gx_group(uint32_t sb, int g, int buf,
                                              int t, int rowbase, int j0,
                                              int gtid) {
    uint32_t dst = sb + GXS + (uint32_t)(g * 2 + buf) * 2304;
    int b = gtid >> 3, rem = gtid & 7;
    int gate = rem >> 1, hf = rem & 1;
    cp16(dst + (uint32_t)(b * 144 + gate * 32 + hf * 16),
         g_Gx + ((size_t)t * Bv + rowbase + b) * Gv + j0 + gate * Hv + hf * 8);
    CP_COMMIT();
}

__global__ void __launch_bounds__(256, 1) lstm_persistent(float* __restrict__ dout)
{
    extern __shared__ char smem[];
    uint32_t sb = smem_u32(smem);
    const int tid = threadIdx.x, lane = tid & 31, wid = tid >> 5;
    const int bg = blockIdx.x >> 6;            // batch group 0/1
    const int b0 = bg * 32;
    const int j0 = (blockIdx.x & 63) * 16;     // first hidden col
    const int g = wid >> 2;                    // row-half group (0: tid<128)
    const int wg = wid & 3;                    // warp-in-group = gate index
    const int gtid = tid & 127;
    const int rowbase = b0 + g * 16;
    const int nbase = wg * 16;
    const int gbufbase = g * 3;
    const unsigned barid = (unsigned)(g + 1);
    unsigned int* barp = &g_bar4[bg * 2 + g];

    // ---- Preload W_f16 tile: 64 gate rows x K=1024 = 128KB (full CTA)
    #pragma unroll
    for (int r = 0; r < 32; r++) {             // 8192 cp16
        int idx = tid + r * 256;
        int chunk = idx >> 9, within = idx & 511;
        int row = within >> 3, c = within & 7;   // row = gate*16 + jc
        int gate = row >> 4, jc = row & 15;
        const __half* src = g_Whh_f16
            + (size_t)(gate * Hv + j0 + jc) * Hv + chunk * 64 + c * 8;
        cp16(sb + WS + chunk * 8192 + SWZ128((uint32_t)(row * 128 + c * 16)), src);
    }
    CP_COMMIT();
    CP_WAIT(0);

    float* GsG = (float*)(smem + GS + (uint32_t)g * 4224);
    float* cs  = (float*)(smem + CS);
    cs[tid] = 0.0f;
    cs[tid + 256] = 0.0f;
    __syncthreads();                            // only full-CTA sync

    // prefetch this group's Gx(0) — per-thread cp group accounting
    load_gx_group(sb, g, 0, 0, rowbase, j0, gtid);

    for (int t = 0; t < Tv; t++) {
        const __half* hIn = g_h[t & 1];
        __half* hOut      = g_h[(t + 1) & 1];

        float acc[2][4];
        #pragma unroll
        for (int i = 0; i < 2; i++)
            #pragma unroll
            for (int j = 0; j < 4; j++) acc[i][j] = 0.0f;

        // prologue: chunks 0,1 (pending {Gx, A0, A1})
        group_loadA(sb, gbufbase + 0, 0,   hIn, rowbase, gtid); CP_COMMIT();
        group_loadA(sb, gbufbase + 1, 256, hIn, rowbase, gtid); CP_COMMIT();

        // group-private pipeline: 4 chunks of K=256
        #pragma unroll
        for (int i = 0; i < 4; i++) {
            if (i < 3) { CP_WAIT(1); } else { CP_WAIT(0); }
            asm volatile("bar.sync %0, 128;" :: "r"(barid) : "memory");
            uint32_t aT = sb + AB + (uint32_t)(gbufbase + (i % 3)) * 8192;
            #pragma unroll
            for (int sub = 0; sub < 4; sub++) {
                int ks = i * 4 + sub;          // global 64-wide sub-chunk
                warp_mma_f16<1, 1>(aT + (uint32_t)sub * 2048,
                                   sb + WS + (uint32_t)ks * 8192,
                                   0, nbase, lane, acc);
            }
            if (i + 2 < 4) {
                group_loadA(sb, gbufbase + ((i + 2) % 3), (i + 2) * 256,
                            hIn, rowbase, gtid);
                CP_COMMIT();
            }
        }

        // Stage this group's complete gate tile (16 rows x 64 cols)
        #pragma unroll
        for (int p = 0; p < 2; p++) {
            float* a = acc[p];
            int r0 = lane >> 2;
            int cc = nbase + p * 8 + 2 * (lane & 3);
            GsG[r0 * 66 + cc]           = a[0];
            GsG[r0 * 66 + cc + 1]       = a[1];
            GsG[(r0 + 8) * 66 + cc]     = a[2];
            GsG[(r0 + 8) * 66 + cc + 1] = a[3];
        }
        asm volatile("bar.sync %0, 128;" :: "r"(barid) : "memory");

        // Group-private cell update: 256 cells (16 rows x 16 cols)
        const __half* gx = (const __half*)(smem + GXS
                            + (uint32_t)(g * 2 + (t & 1)) * 2304);
        float hn_s[2], cn_s[2];
        #pragma unroll
        for (int p = 0; p < 2; p++) {
            int cell = gtid + p * 128;
            int b = cell >> 4, jc = cell & 15;
            const __half* gxr = gx + b * 72;
            float gi = GsG[b * 66 + jc]      + __half2float(gxr[jc]);
            float gf = GsG[b * 66 + 16 + jc] + __half2float(gxr[16 + jc]);
            float gg = GsG[b * 66 + 32 + jc] + __half2float(gxr[32 + jc]);
            float go = GsG[b * 66 + 48 + jc] + __half2float(gxr[48 + jc]);

            int ci = g * 256 + cell;
            float c_old = cs[ci];
            float cn = sigm(gf) * c_old + sigm(gi) * tanh_fast(gg);
            float hn = sigm(go) * tanh_fast(cn);
            cs[ci] = cn;
            hn_s[p] = hn; cn_s[p] = cn;

            hOut[(size_t)(rowbase + b) * Hv + j0 + jc] = __float2half(hn);
        }
        asm volatile("bar.sync %0, 128;" :: "r"(barid) : "memory");

        // prefetch next step's Gx (group-private buffer, own cp group)
        if (t + 1 < Tv) load_gx_group(sb, g, (t + 1) & 1, t + 1, rowbase, j0, gtid);

        // arrive: this group's h(t+1) rows published
        if (gtid == 0) {
            unsigned int ignored;
            asm volatile("atom.add.release.gpu.u32 %0, [%1], 1;"
                         : "=r"(ignored) : "l"(barp) : "memory");
        }

        // off-critical-path: stream outputs to DRAM
        #pragma unroll
        for (int p = 0; p < 2; p++) {
            int cell = gtid + p * 128;
            int b = cell >> 4, jc = cell & 15;
            int batch = rowbase + b;
            dout[(size_t)batch * Tv * Hv + (size_t)t * Hv + j0 + jc] = hn_s[p];
            if (t == Tv - 1) {
                size_t obase = (size_t)Bv * Tv * Hv;
                int hidx = batch * Hv + j0 + jc;
                dout[obase + hidx] = hn_s[p];                    // h_T
                dout[obase + (size_t)Bv * Hv + hidx] = cn_s[p];  // c_T
            }
        }

        // spin for the 64 producer arrivals of this (bg, g) row-half
        if (gtid == 0) {
            unsigned int target = 64u * (unsigned int)(t + 1);
            unsigned int cur;
            do {
                asm volatile("ld.acquire.gpu.u32 %0, [%1];"
                             : "=r"(cur) : "l"(barp) : "memory");
                if (cur >= target) break;
                asm volatile("nanosleep.u32 16;");
            } while (true);
        }
        asm volatile("bar.sync %0, 128;" :: "r"(barid) : "memory");
    }
}

// ---------------------------------------------------------------------------
// Launch: prep_all(1), gemm(2), dummy(3), persistent(4) — keeps ncu -s 5
// capturing lstm_persistent.
// ---------------------------------------------------------------------------
extern "C" void kernel_launch(void* const* d_in, const int* in_sizes, int n_in,
                              void* d_out, int out_size)
{
    const float* x    = (const float*)d_in[0];  // [B, T, I]
    const float* Wih  = (const float*)d_in[1];  // [4H, I]
    const float* Whh  = (const float*)d_in[2];  // [4H, H]
    const float* bias = (const float*)d_in[3];  // [4H]
    float* out = (float*)d_out;
    (void)in_sizes; (void)n_in; (void)out_size;

    cudaFuncSetAttribute(gemm_in_mma,     cudaFuncAttributeMaxDynamicSharedMemorySize, G_SMEM);
    cudaFuncSetAttribute(lstm_persistent, cudaFuncAttributeMaxDynamicSharedMemorySize, P_SMEM);

    prep_all<<<4096, 256>>>(x, Wih, Whh);

    dim3 ggrid(Gv / 128, (Bv * Tv) / 128);   // (32, 256)
    gemm_in_mma<<<ggrid, 256, G_SMEM>>>(bias);

    dummy_kernel<<<1, 32>>>();

    lstm_persistent<<<128, 256, P_SMEM>>>(out);
}

// round 16
// speedup vs baseline: 1.0657x; 1.0657x over previous
#include <cuda_runtime.h>
#include <cuda_bf16.h>
#include <cuda_fp16.h>
#include <cstdint>
#include <math.h>

#define Bv 64
#define Tv 512
#define Iv 1024
#define Hv 1024
#define Gv 4096   // 4*H

// ---------------------------------------------------------------------------
// Static device scratch (all fp16)
// ---------------------------------------------------------------------------
__device__ __half g_Gx[(size_t)Tv * Bv * Gv];             // 256MB [T][B][4H]
__device__ __half g_x_f16[(size_t)Bv * Tv * Iv];          // 64MB
__device__ __half g_Wih_f16[(size_t)Gv * Iv];             // 8MB
__device__ __half g_Whh_f16[(size_t)Gv * Hv];             // 8MB
__device__ __half g_h[2][Bv * Hv];                        // fp16 h
__device__ unsigned int g_bar2[2];                        // per-batch-group

// ---------------------------------------------------------------------------
// Helpers
// ---------------------------------------------------------------------------
__device__ __forceinline__ uint32_t smem_u32(const void* p) {
    uint32_t a;
    asm("{ .reg .u64 t; cvta.to.shared.u64 t, %1; cvt.u32.u64 %0, t; }"
        : "=r"(a) : "l"(p));
    return a;
}

#define SWZ128(o) ((o) ^ (((o) >> 3) & 0x70))

__device__ __forceinline__ void cp16(uint32_t dst, const void* src) {
    asm volatile("cp.async.cg.shared.global [%0], [%1], 16;" :: "r"(dst), "l"(src));
}
#define CP_COMMIT() asm volatile("cp.async.commit_group;" ::: "memory")
#define CP_WAIT(n)  asm volatile("cp.async.wait_group %0;" :: "n"(n) : "memory")

__device__ __forceinline__ void ldsm4(uint32_t* r, uint32_t addr) {
    asm volatile("ldmatrix.sync.aligned.m8n8.x4.shared.b16 {%0,%1,%2,%3}, [%4];"
        : "=r"(r[0]), "=r"(r[1]), "=r"(r[2]), "=r"(r[3]) : "r"(addr));
}

__device__ __forceinline__ void mma16816h(float* d, const uint32_t* a,
                                          uint32_t b0, uint32_t b1) {
    asm volatile(
        "mma.sync.aligned.m16n8k16.row.col.f32.f16.f16.f32 "
        "{%0,%1,%2,%3}, {%4,%5,%6,%7}, {%8,%9}, {%0,%1,%2,%3};"
        : "+f"(d[0]), "+f"(d[1]), "+f"(d[2]), "+f"(d[3])
        : "r"(a[0]), "r"(a[1]), "r"(a[2]), "r"(a[3]), "r"(b0), "r"(b1));
}

__device__ __forceinline__ float sigm(float x) {
    return 1.0f / (1.0f + __expf(-x));
}
__device__ __forceinline__ float tanh_fast(float x) {
    float cx = fminf(fmaxf(x, -10.0f), 10.0f);
    float e = __expf(2.0f * cx);
    return (e - 1.0f) / (e + 1.0f);
}

// ---------------------------------------------------------------------------
// fp16 single-pass warp MMA over one 64-wide K sub-tile.
// MT m-tiles of 16 rows, NT n-tiles of 16 cols.
// ---------------------------------------------------------------------------
template <int MT, int NT>
__device__ __forceinline__ void warp_mma_f16(
    uint32_t aT, uint32_t bT, int mrow, int nbase, int lane, float acc[][4])
{
    const int arowoff = (lane & 7) + ((lane >> 3) & 1) * 8;
    const int nrowoff = (lane & 7) + ((lane >> 4) & 1) * 8;
    #pragma unroll
    for (int kk = 0; kk < 4; kk++) {
        uint32_t ah[MT][4], bw[NT][4];
        const int akoff = kk * 32 + (lane >> 4) * 16;
        const int bkoff = kk * 32 + ((lane >> 3) & 1) * 16;
        #pragma unroll
        for (int m = 0; m < MT; m++) {
            uint32_t off = SWZ128((uint32_t)((mrow + m * 16 + arowoff) * 128 + akoff));
            ldsm4(ah[m], aT + off);
        }
        #pragma unroll
        for (int jb = 0; jb < NT; jb++) {
            uint32_t off = SWZ128((uint32_t)((nbase + jb * 16 + nrowoff) * 128 + bkoff));
            ldsm4(bw[jb], bT + off);
        }
        #pragma unroll
        for (int jb = 0; jb < NT; jb++)
            #pragma unroll
            for (int m = 0; m < MT; m++) {
                mma16816h(acc[m * 2 * NT + jb * 2],     ah[m], bw[jb][0], bw[jb][1]);
                mma16816h(acc[m * 2 * NT + jb * 2 + 1], ah[m], bw[jb][2], bw[jb][3]);
            }
    }
}

// ---------------------------------------------------------------------------
// Fused prep (device symbols bound in device code — R3 lesson).
// ---------------------------------------------------------------------------
__global__ void prep_all(const float* __restrict__ x,
                         const float* __restrict__ Wih,
                         const float* __restrict__ Whh) {
    const size_t NX = (size_t)Bv * Tv * Iv;
    const size_t NW = (size_t)Gv * Iv;
    size_t gid = (size_t)blockIdx.x * blockDim.x + threadIdx.x;
    size_t stride = (size_t)gridDim.x * blockDim.x;
    for (size_t i = gid; i < NX; i += stride) g_x_f16[i]   = __float2half(x[i]);
    for (size_t i = gid; i < NW; i += stride) g_Wih_f16[i] = __float2half(Wih[i]);
    for (size_t i = gid; i < NW; i += stride) g_Whh_f16[i] = __float2half(Whh[i]);
    for (size_t i = gid; i < (size_t)Bv * Hv; i += stride) g_h[0][i] = __float2half(0.0f);
    if (gid < 2) g_bar2[gid] = 0u;
}

__global__ void dummy_kernel() {}

// ---------------------------------------------------------------------------
// Input GEMM (fp16 single-pass HMMA, proven R12-R14)
// ---------------------------------------------------------------------------
#define G_STAGE 32768
#define G_SMEM  (2 * G_STAGE)

__device__ __forceinline__ void gemm_load(uint32_t sb, int s, int k0,
                                          int m0, int n0, int tid) {
    uint32_t base = sb + (uint32_t)s * G_STAGE;
    #pragma unroll
    for (int r = 0; r < 4; r++) {
        int idx = tid + r * 256;
        int row = idx >> 3, c = idx & 7;
        cp16(base + SWZ128((uint32_t)(row * 128 + c * 16)),
             g_x_f16 + (size_t)(m0 + row) * Iv + k0 + c * 8);
    }
    #pragma unroll
    for (int r = 0; r < 4; r++) {
        int idx = tid + r * 256;
        int row = idx >> 3, c = idx & 7;
        cp16(base + 16384 + SWZ128((uint32_t)(row * 128 + c * 16)),
             g_Wih_f16 + (size_t)(n0 + row) * Iv + k0 + c * 8);
    }
}

__global__ void __launch_bounds__(256, 1) gemm_in_mma(const float* __restrict__ bias)
{
    extern __shared__ char smem[];
    uint32_t sb = smem_u32(smem);
    const int tid = threadIdx.x, lane = tid & 31, wid = tid >> 5;
    const int m0 = blockIdx.y * 128, n0 = blockIdx.x * 128;

    float acc[16][4];
    #pragma unroll
    for (int i = 0; i < 16; i++)
        #pragma unroll
        for (int j = 0; j < 4; j++) acc[i][j] = 0.0f;

    gemm_load(sb, 0, 0, m0, n0, tid);
    CP_COMMIT();

    const int mrow = (wid & 3) * 32, nbase = (wid >> 2) * 64;
    for (int it = 0; it < 16; it++) {
        const int s = it & 1;
        if (it + 1 < 16) {
            gemm_load(sb, (it + 1) & 1, (it + 1) * 64, m0, n0, tid);
            CP_COMMIT();
            CP_WAIT(1);
        } else {
            CP_WAIT(0);
        }
        __syncthreads();
        uint32_t base = sb + (uint32_t)s * G_STAGE;
        warp_mma_f16<2, 4>(base, base + 16384, mrow, nbase, lane, acc);
        __syncthreads();
    }

    #pragma unroll
    for (int m = 0; m < 2; m++)
        #pragma unroll
        for (int j = 0; j < 8; j++) {
            float* a = acc[m * 8 + j];
            int gr = m0 + (wid & 3) * 32 + m * 16 + (lane >> 2);
            int n  = n0 + (wid >> 2) * 64 + j * 8 + 2 * (lane & 3);
            float b0 = bias[n], b1 = bias[n + 1];
            int bi0 = gr >> 9, tt0 = gr & 511;
            __half2* o0 = (__half2*)(g_Gx + ((size_t)tt0 * Bv + bi0) * Gv + n);
            *o0 = __floats2half2_rn(a[0] + b0, a[1] + b1);
            int gr2 = gr + 8, bi2 = gr2 >> 9, tt2 = gr2 & 511;
            __half2* o2 = (__half2*)(g_Gx + ((size_t)tt2 * Bv + bi2) * Gv + n);
            *o2 = __floats2half2_rn(a[2] + b0, a[3] + b1);
        }
}

// ---------------------------------------------------------------------------
// Persistent LSTM recurrence (R14 base + R16 coarse chunks):
// 128 CTAs = 2 batch-groups x 64. CTA = 32 batch rows x 16 hidden cols
// (64 gate rows). W_f16 tile 128KB SMEM-resident. Parity-group pipelines
// with named barriers — now 2 chunks of K=256 per group (was 4 of K=128):
// 2 waits + 2 named barriers per step. Per-batch-group global barriers.
// ---------------------------------------------------------------------------
#define WS     0                           /* 16 sub-chunks x 8KB = 128KB */
#define AB     131072                      /* 2 grp x 2 bufs x 16KB = 64KB */
#define GXS    (AB + 4 * 16384)            /* 196608: 2 x 4608 (fp16 144B/row) */
#define CS     (GXS + 2 * 4608)            /* 205824: 512 fp32 = 2KB */
#define GS0    (CS + 2048)                 /* 207872: 32 x 66 fp32 = 8448 */
#define GS1    (GS0 + 8448)                /* 216320 */
#define P_SMEM (GS1 + 8448)                /* 224768 (~219.5KB) */

// Group (128 threads) loads one K-chunk of 256 for 32 batch rows (16KB).
__device__ __forceinline__ void group_loadA(uint32_t sb, int buf, int k0,
                                            const __half* __restrict__ hIn,
                                            int b0, int gtid) {
    uint32_t base = sb + AB + (uint32_t)buf * 16384;
    #pragma unroll
    for (int r = 0; r < 8; r++) {          // 1024 cp16 = 16KB
        int idx = gtid + r * 128;
        int sub = idx >> 8, rem = idx & 255;   // sub 0..3 (64-wide)
        int row = rem >> 3, c = rem & 7;       // row = 0..31
        const __half* src = hIn + (size_t)(b0 + row) * Hv + k0 + sub * 64 + c * 8;
        cp16(base + sub * 4096 + SWZ128((uint32_t)(row * 128 + c * 16)), src);
    }
}

// Gx prefetch — GROUP0 ONLY (tid < 128), 2 cp16 per thread, own group.
__device__ __forceinline__ void load_gx_g0(uint32_t sb, int buf, int t,
                                           int b0, int j0, int tid) {
    const __half* gxbase = g_Gx + ((size_t)t * Bv + b0) * Gv + j0;
    uint32_t dst = sb + GXS + (uint32_t)buf * 4608;
    #pragma unroll
    for (int r = 0; r < 2; r++) {          // 256 cp16 = 4KB
        int idx = tid + r * 128;           // 0..255
        int b = idx >> 3, rem = idx & 7;
        int gate = rem >> 1, hf = rem & 1;
        cp16(dst + (uint32_t)(b * 144 + gate * 32 + hf * 16),
             gxbase + (size_t)b * Gv + gate * Hv + hf * 8);
    }
    CP_COMMIT();
}

__global__ void __launch_bounds__(256, 1) lstm_persistent(float* __restrict__ dout)
{
    extern __shared__ char smem[];
    uint32_t sb = smem_u32(smem);
    const int tid = threadIdx.x, lane = tid & 31, wid = tid >> 5;
    const int bg = blockIdx.x >> 6;            // batch group 0/1
    const int b0 = bg * 32;                    // first batch row
    const int j0 = (blockIdx.x & 63) * 16;     // first hidden col
    const int g = wid >> 2;                    // K-parity group (0: tid<128)
    const int gtid = tid & 127;
    const int mrow = (wid & 1) * 16;           // m16 tile
    const int nbase = ((wid >> 1) & 1) * 32;   // n32 (2 n-tiles of 16)
    const int bufbase = g * 2;
    const unsigned barid = (unsigned)(g + 1);
    unsigned int* barp = &g_bar2[bg];

    // ---- Preload W_f16 tile: 64 gate rows x K=1024 = 128KB, sub-chunk-major
    #pragma unroll
    for (int r = 0; r < 32; r++) {             // 8192 cp16
        int idx = tid + r * 256;
        int chunk = idx >> 9, within = idx & 511;
        int row = within >> 3, c = within & 7;   // row = gate*16 + jc (0..63)
        int gate = row >> 4, jc = row & 15;
        const __half* src = g_Whh_f16
            + (size_t)(gate * Hv + j0 + jc) * Hv + chunk * 64 + c * 8;
        cp16(sb + WS + chunk * 8192 + SWZ128((uint32_t)(row * 128 + c * 16)), src);
    }
    CP_COMMIT();
    CP_WAIT(0);
    __syncthreads();

    float* Gs0 = (float*)(smem + GS0);
    float* Gs1 = (float*)(smem + GS1);
    float* cs  = (float*)(smem + CS);
    cs[tid] = 0.0f;
    cs[tid + 256] = 0.0f;

    // prefetch Gx(0) — group0's pending ladder accounts for it
    if (g == 0) load_gx_g0(sb, 0, 0, b0, j0, tid);
    __syncthreads();

    for (int t = 0; t < Tv; t++) {
        const __half* hIn = g_h[t & 1];
        __half* hOut      = g_h[(t + 1) & 1];

        float acc[4][4];
        #pragma unroll
        for (int i = 0; i < 4; i++)
            #pragma unroll
            for (int j = 0; j < 4; j++) acc[i][j] = 0.0f;

        // prologue: this group's two K=256 parity chunks (c = g, g+2)
        group_loadA(sb, bufbase + 0, (g)     * 256, hIn, b0, gtid); CP_COMMIT();
        group_loadA(sb, bufbase + 1, (g + 2) * 256, hIn, b0, gtid); CP_COMMIT();

        // 2-iteration group-private pipeline
        // group0 pending at i=0: {Gx,A0,A1} -> WAIT(1) completes Gx+A0;
        // group1 pending at i=0: {A0,A1}    -> WAIT(1) completes A0.
        #pragma unroll
        for (int i = 0; i < 2; i++) {
            if (i == 0) { CP_WAIT(1); } else { CP_WAIT(0); }
            asm volatile("bar.sync %0, 128;" :: "r"(barid) : "memory");
            const int c = g + 2 * i;           // K=256 chunk index
            uint32_t aT = sb + AB + (uint32_t)(bufbase + i) * 16384;
            #pragma unroll
            for (int sub = 0; sub < 4; sub++) {
                int ks = c * 4 + sub;          // global 64-wide sub-chunk
                warp_mma_f16<1, 2>(aT + (uint32_t)sub * 4096,
                                   sb + WS + (uint32_t)ks * 8192,
                                   mrow, nbase, lane, acc);
            }
        }

        // Stage partial gates (per parity buffer), then CTA-wide join
        float* Gs = g ? Gs1 : Gs0;
        #pragma unroll
        for (int jb = 0; jb < 2; jb++)
            #pragma unroll
            for (int p = 0; p < 2; p++) {
                float* a = acc[jb * 2 + p];
                int r0 = mrow + (lane >> 2);
                int cc = nbase + jb * 16 + p * 8 + 2 * (lane & 3);
                Gs[r0 * 66 + cc]           = a[0];
                Gs[r0 * 66 + cc + 1]       = a[1];
                Gs[(r0 + 8) * 66 + cc]     = a[2];
                Gs[(r0 + 8) * 66 + cc + 1] = a[3];
            }
        __syncthreads();

        // Fused cell update: 512 cells (32 batch x 16 hidden cols)
        const __half* gx = (const __half*)(smem + GXS + (uint32_t)(t & 1) * 4608);
        float hn_s[2], cn_s[2];
        #pragma unroll
        for (int p = 0; p < 2; p++) {
            int cell = tid + p * 256;
            int b = cell >> 4, jc = cell & 15;
            const __half* gxr = gx + b * 72;
            float gi = Gs0[b * 66 + jc]      + Gs1[b * 66 + jc]      + __half2float(gxr[jc]);
            float gf = Gs0[b * 66 + 16 + jc] + Gs1[b * 66 + 16 + jc] + __half2float(gxr[16 + jc]);
            float gg = Gs0[b * 66 + 32 + jc] + Gs1[b * 66 + 32 + jc] + __half2float(gxr[32 + jc]);
            float go = Gs0[b * 66 + 48 + jc] + Gs1[b * 66 + 48 + jc] + __half2float(gxr[48 + jc]);

            float c_old = cs[cell];
            float cn = sigm(gf) * c_old + sigm(gi) * tanh_fast(gg);
            float hn = sigm(go) * tanh_fast(cn);
            cs[cell] = cn;
            hn_s[p] = hn; cn_s[p] = cn;

            hOut[(size_t)(b0 + b) * Hv + j0 + jc] = __float2half(hn);
        }
        __syncthreads();

        // prefetch next step's Gx during the barrier window (group0 only)
        if (g == 0 && t + 1 < Tv) load_gx_g0(sb, (t + 1) & 1, t + 1, b0, j0, tid);

        // arrive: this CTA's h(t+1) rows published (group-local barrier)
        if (tid == 0) {
            unsigned int ignored;
            asm volatile("atom.add.release.gpu.u32 %0, [%1], 1;"
                         : "=r"(ignored) : "l"(barp) : "memory");
        }

        // off-critical-path: stream outputs to DRAM
        #pragma unroll
        for (int p = 0; p < 2; p++) {
            int cell = tid + p * 256;
            int b = cell >> 4, jc = cell & 15;
            int batch = b0 + b;
            dout[(size_t)batch * Tv * Hv + (size_t)t * Hv + j0 + jc] = hn_s[p];
            if (t == Tv - 1) {
                size_t obase = (size_t)Bv * Tv * Hv;
                int hidx = batch * Hv + j0 + jc;
                dout[obase + hidx] = hn_s[p];                    // h_T
                dout[obase + (size_t)Bv * Hv + hidx] = cn_s[p];  // c_T
            }
        }

        // spin for this batch-group's 64 arrivals of step t
        if (tid == 0) {
            unsigned int target = 64u * (unsigned int)(t + 1);
            unsigned int cur;
            do {
                asm volatile("ld.acquire.gpu.u32 %0, [%1];"
                             : "=r"(cur) : "l"(barp) : "memory");
                if (cur >= target) break;
                asm volatile("nanosleep.u32 8;");
            } while (true);
        }
        __syncthreads();
    }
}

// ---------------------------------------------------------------------------
// Launch: prep_all(1), gemm(2), dummy(3), persistent(4) — keeps ncu -s 5
// capturing lstm_persistent.
// ---------------------------------------------------------------------------
extern "C" void kernel_launch(void* const* d_in, const int* in_sizes, int n_in,
                              void* d_out, int out_size)
{
    const float* x    = (const float*)d_in[0];  // [B, T, I]
    const float* Wih  = (const float*)d_in[1];  // [4H, I]
    const float* Whh  = (const float*)d_in[2];  // [4H, H]
    const float* bias = (const float*)d_in[3];  // [4H]
    float* out = (float*)d_out;
    (void)in_sizes; (void)n_in; (void)out_size;

    cudaFuncSetAttribute(gemm_in_mma,     cudaFuncAttributeMaxDynamicSharedMemorySize, G_SMEM);
    cudaFuncSetAttribute(lstm_persistent, cudaFuncAttributeMaxDynamicSharedMemorySize, P_SMEM);

    prep_all<<<4096, 256>>>(x, Wih, Whh);

    dim3 ggrid(Gv / 128, (Bv * Tv) / 128);   // (32, 256)
    gemm_in_mma<<<ggrid, 256, G_SMEM>>>(bias);

    dummy_kernel<<<1, 32>>>();

    lstm_persistent<<<128, 256, P_SMEM>>>(out);
}

// round 17
// speedup vs baseline: 1.1202x; 1.0512x over previous
#include <cuda_runtime.h>
#include <cuda_bf16.h>
#include <cuda_fp16.h>
#include <cstdint>
#include <math.h>

#define Bv 64
#define Tv 512
#define Iv 1024
#define Hv 1024
#define Gv 4096   // 4*H

// ---------------------------------------------------------------------------
// Static device scratch (all fp16)
// ---------------------------------------------------------------------------
__device__ __half g_Gx[(size_t)Tv * Bv * Gv];             // 256MB [T][B][4H]
__device__ __half g_x_f16[(size_t)Bv * Tv * Iv];          // 64MB
__device__ __half g_Wih_f16[(size_t)Gv * Iv];             // 8MB
__device__ __half g_Whh_f16[(size_t)Gv * Hv];             // 8MB
__device__ __half g_h[2][Bv * Hv];                        // fp16 h
__device__ unsigned int g_bar2[2];                        // per-batch-group

// ---------------------------------------------------------------------------
// Helpers
// ---------------------------------------------------------------------------
__device__ __forceinline__ uint32_t smem_u32(const void* p) {
    uint32_t a;
    asm("{ .reg .u64 t; cvta.to.shared.u64 t, %1; cvt.u32.u64 %0, t; }"
        : "=r"(a) : "l"(p));
    return a;
}

#define SWZ128(o) ((o) ^ (((o) >> 3) & 0x70))

__device__ __forceinline__ void cp16(uint32_t dst, const void* src) {
    asm volatile("cp.async.cg.shared.global [%0], [%1], 16;" :: "r"(dst), "l"(src));
}
#define CP_COMMIT() asm volatile("cp.async.commit_group;" ::: "memory")
#define CP_WAIT(n)  asm volatile("cp.async.wait_group %0;" :: "n"(n) : "memory")

__device__ __forceinline__ void ldsm4(uint32_t* r, uint32_t addr) {
    asm volatile("ldmatrix.sync.aligned.m8n8.x4.shared.b16 {%0,%1,%2,%3}, [%4];"
        : "=r"(r[0]), "=r"(r[1]), "=r"(r[2]), "=r"(r[3]) : "r"(addr));
}

__device__ __forceinline__ void mma16816h(float* d, const uint32_t* a,
                                          uint32_t b0, uint32_t b1) {
    asm volatile(
        "mma.sync.aligned.m16n8k16.row.col.f32.f16.f16.f32 "
        "{%0,%1,%2,%3}, {%4,%5,%6,%7}, {%8,%9}, {%0,%1,%2,%3};"
        : "+f"(d[0]), "+f"(d[1]), "+f"(d[2]), "+f"(d[3])
        : "r"(a[0]), "r"(a[1]), "r"(a[2]), "r"(a[3]), "r"(b0), "r"(b1));
}

__device__ __forceinline__ float sigm(float x) {
    return 1.0f / (1.0f + __expf(-x));
}
__device__ __forceinline__ float tanh_fast(float x) {
    float cx = fminf(fmaxf(x, -10.0f), 10.0f);
    float e = __expf(2.0f * cx);
    return (e - 1.0f) / (e + 1.0f);
}

// ---------------------------------------------------------------------------
// fp16 single-pass warp MMA over one 64-wide K sub-tile.
// MT m-tiles of 16 rows, NT n-tiles of 16 cols.
// ---------------------------------------------------------------------------
template <int MT, int NT>
__device__ __forceinline__ void warp_mma_f16(
    uint32_t aT, uint32_t bT, int mrow, int nbase, int lane, float acc[][4])
{
    const int arowoff = (lane & 7) + ((lane >> 3) & 1) * 8;
    const int nrowoff = (lane & 7) + ((lane >> 4) & 1) * 8;
    #pragma unroll
    for (int kk = 0; kk < 4; kk++) {
        uint32_t ah[MT][4], bw[NT][4];
        const int akoff = kk * 32 + (lane >> 4) * 16;
        const int bkoff = kk * 32 + ((lane >> 3) & 1) * 16;
        #pragma unroll
        for (int m = 0; m < MT; m++) {
            uint32_t off = SWZ128((uint32_t)((mrow + m * 16 + arowoff) * 128 + akoff));
            ldsm4(ah[m], aT + off);
        }
        #pragma unroll
        for (int jb = 0; jb < NT; jb++) {
            uint32_t off = SWZ128((uint32_t)((nbase + jb * 16 + nrowoff) * 128 + bkoff));
            ldsm4(bw[jb], bT + off);
        }
        #pragma unroll
        for (int jb = 0; jb < NT; jb++)
            #pragma unroll
            for (int m = 0; m < MT; m++) {
                mma16816h(acc[m * 2 * NT + jb * 2],     ah[m], bw[jb][0], bw[jb][1]);
                mma16816h(acc[m * 2 * NT + jb * 2 + 1], ah[m], bw[jb][2], bw[jb][3]);
            }
    }
}

// ---------------------------------------------------------------------------
// Fused prep (device symbols bound in device code — R3 lesson).
// ---------------------------------------------------------------------------
__global__ void prep_all(const float* __restrict__ x,
                         const float* __restrict__ Wih,
                         const float* __restrict__ Whh) {
    const size_t NX = (size_t)Bv * Tv * Iv;
    const size_t NW = (size_t)Gv * Iv;
    size_t gid = (size_t)blockIdx.x * blockDim.x + threadIdx.x;
    size_t stride = (size_t)gridDim.x * blockDim.x;
    for (size_t i = gid; i < NX; i += stride) g_x_f16[i]   = __float2half(x[i]);
    for (size_t i = gid; i < NW; i += stride) g_Wih_f16[i] = __float2half(Wih[i]);
    for (size_t i = gid; i < NW; i += stride) g_Whh_f16[i] = __float2half(Whh[i]);
    for (size_t i = gid; i < (size_t)Bv * Hv; i += stride) g_h[0][i] = __float2half(0.0f);
    if (gid < 2) g_bar2[gid] = 0u;
}

__global__ void dummy_kernel() {}

// ---------------------------------------------------------------------------
// Input GEMM (fp16 single-pass HMMA) — R17: occupancy 2 (was 1). The second
// co-resident CTA hides the 2-stage pipeline's wait/sync bubbles.
// ---------------------------------------------------------------------------
#define G_STAGE 32768
#define G_SMEM  (2 * G_STAGE)

__device__ __forceinline__ void gemm_load(uint32_t sb, int s, int k0,
                                          int m0, int n0, int tid) {
    uint32_t base = sb + (uint32_t)s * G_STAGE;
    #pragma unroll
    for (int r = 0; r < 4; r++) {
        int idx = tid + r * 256;
        int row = idx >> 3, c = idx & 7;
        cp16(base + SWZ128((uint32_t)(row * 128 + c * 16)),
             g_x_f16 + (size_t)(m0 + row) * Iv + k0 + c * 8);
    }
    #pragma unroll
    for (int r = 0; r < 4; r++) {
        int idx = tid + r * 256;
        int row = idx >> 3, c = idx & 7;
        cp16(base + 16384 + SWZ128((uint32_t)(row * 128 + c * 16)),
             g_Wih_f16 + (size_t)(n0 + row) * Iv + k0 + c * 8);
    }
}

__global__ void __launch_bounds__(256, 2) gemm_in_mma(const float* __restrict__ bias)
{
    extern __shared__ char smem[];
    uint32_t sb = smem_u32(smem);
    const int tid = threadIdx.x, lane = tid & 31, wid = tid >> 5;
    const int m0 = blockIdx.y * 128, n0 = blockIdx.x * 128;

    float acc[16][4];
    #pragma unroll
    for (int i = 0; i < 16; i++)
        #pragma unroll
        for (int j = 0; j < 4; j++) acc[i][j] = 0.0f;

    gemm_load(sb, 0, 0, m0, n0, tid);
    CP_COMMIT();

    const int mrow = (wid & 3) * 32, nbase = (wid >> 2) * 64;
    for (int it = 0; it < 16; it++) {
        const int s = it & 1;
        if (it + 1 < 16) {
            gemm_load(sb, (it + 1) & 1, (it + 1) * 64, m0, n0, tid);
            CP_COMMIT();
            CP_WAIT(1);
        } else {
            CP_WAIT(0);
        }
        __syncthreads();
        uint32_t base = sb + (uint32_t)s * G_STAGE;
        warp_mma_f16<2, 4>(base, base + 16384, mrow, nbase, lane, acc);
        __syncthreads();
    }

    #pragma unroll
    for (int m = 0; m < 2; m++)
        #pragma unroll
        for (int j = 0; j < 8; j++) {
            float* a = acc[m * 8 + j];
            int gr = m0 + (wid & 3) * 32 + m * 16 + (lane >> 2);
            int n  = n0 + (wid >> 2) * 64 + j * 8 + 2 * (lane & 3);
            float b0 = bias[n], b1 = bias[n + 1];
            int bi0 = gr >> 9, tt0 = gr & 511;
            __half2* o0 = (__half2*)(g_Gx + ((size_t)tt0 * Bv + bi0) * Gv + n);
            *o0 = __floats2half2_rn(a[0] + b0, a[1] + b1);
            int gr2 = gr + 8, bi2 = gr2 >> 9, tt2 = gr2 & 511;
            __half2* o2 = (__half2*)(g_Gx + ((size_t)tt2 * Bv + bi2) * Gv + n);
            *o2 = __floats2half2_rn(a[2] + b0, a[3] + b1);
        }
}

// ---------------------------------------------------------------------------
// Persistent LSTM recurrence (R16 verbatim — best known):
// 128 CTAs = 2 batch-groups x 64. CTA = 32 batch rows x 16 hidden cols
// (64 gate rows). W_f16 tile 128KB SMEM-resident. Parity-group pipelines
// with named barriers — 2 chunks of K=256 per group. Per-batch-group
// global barriers.
// ---------------------------------------------------------------------------
#define WS     0                           /* 16 sub-chunks x 8KB = 128KB */
#define AB     131072                      /* 2 grp x 2 bufs x 16KB = 64KB */
#define GXS    (AB + 4 * 16384)            /* 196608: 2 x 4608 (fp16 144B/row) */
#define CS     (GXS + 2 * 4608)            /* 205824: 512 fp32 = 2KB */
#define GS0    (CS + 2048)                 /* 207872: 32 x 66 fp32 = 8448 */
#define GS1    (GS0 + 8448)                /* 216320 */
#define P_SMEM (GS1 + 8448)                /* 224768 (~219.5KB) */

// Group (128 threads) loads one K-chunk of 256 for 32 batch rows (16KB).
__device__ __forceinline__ void group_loadA(uint32_t sb, int buf, int k0,
                                            const __half* __restrict__ hIn,
                                            int b0, int gtid) {
    uint32_t base = sb + AB + (uint32_t)buf * 16384;
    #pragma unroll
    for (int r = 0; r < 8; r++) {          // 1024 cp16 = 16KB
        int idx = gtid + r * 128;
        int sub = idx >> 8, rem = idx & 255;   // sub 0..3 (64-wide)
        int row = rem >> 3, c = rem & 7;       // row = 0..31
        const __half* src = hIn + (size_t)(b0 + row) * Hv + k0 + sub * 64 + c * 8;
        cp16(base + sub * 4096 + SWZ128((uint32_t)(row * 128 + c * 16)), src);
    }
}

// Gx prefetch — GROUP0 ONLY (tid < 128), 2 cp16 per thread, own group.
__device__ __forceinline__ void load_gx_g0(uint32_t sb, int buf, int t,
                                           int b0, int j0, int tid) {
    const __half* gxbase = g_Gx + ((size_t)t * Bv + b0) * Gv + j0;
    uint32_t dst = sb + GXS + (uint32_t)buf * 4608;
    #pragma unroll
    for (int r = 0; r < 2; r++) {          // 256 cp16 = 4KB
        int idx = tid + r * 128;           // 0..255
        int b = idx >> 3, rem = idx & 7;
        int gate = rem >> 1, hf = rem & 1;
        cp16(dst + (uint32_t)(b * 144 + gate * 32 + hf * 16),
             gxbase + (size_t)b * Gv + gate * Hv + hf * 8);
    }
    CP_COMMIT();
}

__global__ void __launch_bounds__(256, 1) lstm_persistent(float* __restrict__ dout)
{
    extern __shared__ char smem[];
    uint32_t sb = smem_u32(smem);
    const int tid = threadIdx.x, lane = tid & 31, wid = tid >> 5;
    const int bg = blockIdx.x >> 6;            // batch group 0/1
    const int b0 = bg * 32;                    // first batch row
    const int j0 = (blockIdx.x & 63) * 16;     // first hidden col
    const int g = wid >> 2;                    // K-parity group (0: tid<128)
    const int gtid = tid & 127;
    const int mrow = (wid & 1) * 16;           // m16 tile
    const int nbase = ((wid >> 1) & 1) * 32;   // n32 (2 n-tiles of 16)
    const int bufbase = g * 2;
    const unsigned barid = (unsigned)(g + 1);
    unsigned int* barp = &g_bar2[bg];

    // ---- Preload W_f16 tile: 64 gate rows x K=1024 = 128KB, sub-chunk-major
    #pragma unroll
    for (int r = 0; r < 32; r++) {             // 8192 cp16
        int idx = tid + r * 256;
        int chunk = idx >> 9, within = idx & 511;
        int row = within >> 3, c = within & 7;   // row = gate*16 + jc (0..63)
        int gate = row >> 4, jc = row & 15;
        const __half* src = g_Whh_f16
            + (size_t)(gate * Hv + j0 + jc) * Hv + chunk * 64 + c * 8;
        cp16(sb + WS + chunk * 8192 + SWZ128((uint32_t)(row * 128 + c * 16)), src);
    }
    CP_COMMIT();
    CP_WAIT(0);
    __syncthreads();

    float* Gs0 = (float*)(smem + GS0);
    float* Gs1 = (float*)(smem + GS1);
    float* cs  = (float*)(smem + CS);
    cs[tid] = 0.0f;
    cs[tid + 256] = 0.0f;

    // prefetch Gx(0) — group0's pending ladder accounts for it
    if (g == 0) load_gx_g0(sb, 0, 0, b0, j0, tid);
    __syncthreads();

    for (int t = 0; t < Tv; t++) {
        const __half* hIn = g_h[t & 1];
        __half* hOut      = g_h[(t + 1) & 1];

        float acc[4][4];
        #pragma unroll
        for (int i = 0; i < 4; i++)
            #pragma unroll
            for (int j = 0; j < 4; j++) acc[i][j] = 0.0f;

        // prologue: this group's two K=256 parity chunks (c = g, g+2)
        group_loadA(sb, bufbase + 0, (g)     * 256, hIn, b0, gtid); CP_COMMIT();
        group_loadA(sb, bufbase + 1, (g + 2) * 256, hIn, b0, gtid); CP_COMMIT();

        // 2-iteration group-private pipeline
        // group0 pending at i=0: {Gx,A0,A1} -> WAIT(1) completes Gx+A0;
        // group1 pending at i=0: {A0,A1}    -> WAIT(1) completes A0.
        #pragma unroll
        for (int i = 0; i < 2; i++) {
            if (i == 0) { CP_WAIT(1); } else { CP_WAIT(0); }
            asm volatile("bar.sync %0, 128;" :: "r"(barid) : "memory");
            const int c = g + 2 * i;           // K=256 chunk index
            uint32_t aT = sb + AB + (uint32_t)(bufbase + i) * 16384;
            #pragma unroll
            for (int sub = 0; sub < 4; sub++) {
                int ks = c * 4 + sub;          // global 64-wide sub-chunk
                warp_mma_f16<1, 2>(aT + (uint32_t)sub * 4096,
                                   sb + WS + (uint32_t)ks * 8192,
                                   mrow, nbase, lane, acc);
            }
        }

        // Stage partial gates (per parity buffer), then CTA-wide join
        float* Gs = g ? Gs1 : Gs0;
        #pragma unroll
        for (int jb = 0; jb < 2; jb++)
            #pragma unroll
            for (int p = 0; p < 2; p++) {
                float* a = acc[jb * 2 + p];
                int r0 = mrow + (lane >> 2);
                int cc = nbase + jb * 16 + p * 8 + 2 * (lane & 3);
                Gs[r0 * 66 + cc]           = a[0];
                Gs[r0 * 66 + cc + 1]       = a[1];
                Gs[(r0 + 8) * 66 + cc]     = a[2];
                Gs[(r0 + 8) * 66 + cc + 1] = a[3];
            }
        __syncthreads();

        // Fused cell update: 512 cells (32 batch x 16 hidden cols)
        const __half* gx = (const __half*)(smem + GXS + (uint32_t)(t & 1) * 4608);
        float hn_s[2], cn_s[2];
        #pragma unroll
        for (int p = 0; p < 2; p++) {
            int cell = tid + p * 256;
            int b = cell >> 4, jc = cell & 15;
            const __half* gxr = gx + b * 72;
            float gi = Gs0[b * 66 + jc]      + Gs1[b * 66 + jc]      + __half2float(gxr[jc]);
            float gf = Gs0[b * 66 + 16 + jc] + Gs1[b * 66 + 16 + jc] + __half2float(gxr[16 + jc]);
            float gg = Gs0[b * 66 + 32 + jc] + Gs1[b * 66 + 32 + jc] + __half2float(gxr[32 + jc]);
            float go = Gs0[b * 66 + 48 + jc] + Gs1[b * 66 + 48 + jc] + __half2float(gxr[48 + jc]);

            float c_old = cs[cell];
            float cn = sigm(gf) * c_old + sigm(gi) * tanh_fast(gg);
            float hn = sigm(go) * tanh_fast(cn);
            cs[cell] = cn;
            hn_s[p] = hn; cn_s[p] = cn;

            hOut[(size_t)(b0 + b) * Hv + j0 + jc] = __float2half(hn);
        }
        __syncthreads();

        // prefetch next step's Gx during the barrier window (group0 only)
        if (g == 0 && t + 1 < Tv) load_gx_g0(sb, (t + 1) & 1, t + 1, b0, j0, tid);

        // arrive: this CTA's h(t+1) rows published (group-local barrier)
        if (tid == 0) {
            unsigned int ignored;
            asm volatile("atom.add.release.gpu.u32 %0, [%1], 1;"
                         : "=r"(ignored) : "l"(barp) : "memory");
        }

        // off-critical-path: stream outputs to DRAM
        #pragma unroll
        for (int p = 0; p < 2; p++) {
            int cell = tid + p * 256;
            int b = cell >> 4, jc = cell & 15;
            int batch = b0 + b;
            dout[(size_t)batch * Tv * Hv + (size_t)t * Hv + j0 + jc] = hn_s[p];
            if (t == Tv - 1) {
                size_t obase = (size_t)Bv * Tv * Hv;
                int hidx = batch * Hv + j0 + jc;
                dout[obase + hidx] = hn_s[p];                    // h_T
                dout[obase + (size_t)Bv * Hv + hidx] = cn_s[p];  // c_T
            }
        }

        // spin for this batch-group's 64 arrivals of step t
        if (tid == 0) {
            unsigned int target = 64u * (unsigned int)(t + 1);
            unsigned int cur;
            do {
                asm volatile("ld.acquire.gpu.u32 %0, [%1];"
                             : "=r"(cur) : "l"(barp) : "memory");
                if (cur >= target) break;
                asm volatile("nanosleep.u32 8;");
            } while (true);
        }
        __syncthreads();
    }
}

// ---------------------------------------------------------------------------
// Launch: prep_all(1), gemm(2), dummy(3), persistent(4) — keeps ncu -s 5
// capturing lstm_persistent.
// ---------------------------------------------------------------------------
extern "C" void kernel_launch(void* const* d_in, const int* in_sizes, int n_in,
                              void* d_out, int out_size)
{
    const float* x    = (const float*)d_in[0];  // [B, T, I]
    const float* Wih  = (const float*)d_in[1];  // [4H, I]
    const float* Whh  = (const float*)d_in[2];  // [4H, H]
    const float* bias = (const float*)d_in[3];  // [4H]
    float* out = (float*)d_out;
    (void)in_sizes; (void)n_in; (void)out_size;

    cudaFuncSetAttribute(gemm_in_mma,     cudaFuncAttributeMaxDynamicSharedMemorySize, G_SMEM);
    cudaFuncSetAttribute(lstm_persistent, cudaFuncAttributeMaxDynamicSharedMemorySize, P_SMEM);

    prep_all<<<4096, 256>>>(x, Wih, Whh);

    dim3 ggrid(Gv / 128, (Bv * Tv) / 128);   // (32, 256)
    gemm_in_mma<<<ggrid, 256, G_SMEM>>>(bias);

    dummy_kernel<<<1, 32>>>();

    lstm_persistent<<<128, 256, P_SMEM>>>(out);
}